// round 17
// baseline (speedup 1.0000x reference)
#include <cuda_runtime.h>
#include <cuda_bf16.h>

// DurationCalculator:
//   weights_argmax[b,y] = duration[b,y] + (y < output_length[b] ? 0 : -10000)
//   durations[b,x]      = count over y of (weights_argmax[b,y] == x), 0 <= x < X
// Output (float32): [ weights_argmax (B*Y) | durations (B*X) ]
//
// ATOMS-free histogram v2 (branch-free match aggregation):
//   - per-warp private u16 histogram [X + 32 dummy slots]; cross-warp races
//     impossible by construction
//   - intra-warp duplicates resolved by __match_any_sync; the update is
//     UNCONDITIONAL for every lane:  idx = (leader && 0<=w<X) ? w : X+lane
//     so there is no divergent branch (no BSSY/BSYNC), and within one
//     instruction all 32 lanes write distinct addresses (leaders -> distinct
//     bins, non-leaders -> distinct per-lane dummies) => race-free LDS/STS.
//   - sequential updates from the same warp are ordered (in-order LSU).
//   - merge: 8 bins/thread, 16x LDS.128 + packed __vadd2 u16 sums, bias-trick
//     int->float (no I2F anywhere), float4 stores.
// Falls back to the proven smem-atomic kernel when X exceeds the smem budget.

#ifndef MASK_PENALTY
#define MASK_PENALTY (-10000)
#endif

#define NT 512
#define NWARP (NT / 32)

#define FBIAS    12599296.0f     // 2^23+2^22 + 16384
#define C_VALID  0x4B404000u     // 0x4B400000 + 16384
#define C_MASKED 0x4B4018F0u     // 0x4B400000 + 16384 - 10000
#define CBIAS    12582912.0f     // 2^23+2^22
#define C_ZERO   0x4B400000u

__global__ void __launch_bounds__(NT)
duration_calc_kernel(const int* __restrict__ duration,
                     const int* __restrict__ output_length,
                     float* __restrict__ w_out,
                     float* __restrict__ h_out,
                     int Y, int X, int hstr)     // hstr = X + 32 (u16 elems)
{
    extern __shared__ unsigned short hist16[];   // [NWARP][hstr]

    const int b    = blockIdx.x;
    const int tid  = threadIdx.x;
    const int wid  = tid >> 5;
    const int lane = tid & 31;

    // Zero all warp histograms (16B vector stores; NWARP*hstr*2 % 16 == 0)
    {
        int4* hz = reinterpret_cast<int4*>(hist16);
        const int nz = (NWARP * hstr) >> 3;      // u16 pairs of 8 per int4
        const int4 z = make_int4(0, 0, 0, 0);
        for (int i = tid; i < nz; i += NT) hz[i] = z;
    }
    __syncthreads();

    const int L = output_length[b];

    unsigned short* __restrict__ myhist = hist16 + wid * hstr;

    const int4* __restrict__ dur4 = reinterpret_cast<const int4*>(duration + (size_t)b * Y);
    float4* __restrict__ w4       = reinterpret_cast<float4*>(w_out + (size_t)b * Y);
    const int n4     = Y >> 2;
    const int kiters = (n4 + NT - 1) / NT;       // uniform trip count (match is collective)
    const int ytail0 = n4 << 2;
    const int titers = (Y - ytail0 + NT - 1) / NT;

    // Branch-free histogram step: every lane does exactly one u16 RMW.
    #define HIST_STEP(wv)                                                     \
    do {                                                                      \
        const unsigned m_ = __match_any_sync(0xFFFFFFFFu, (wv));              \
        const int ldr_ = __ffs(m_) - 1;                                       \
        const int cnt_ = __popc(m_);                                          \
        const bool ok_ = (lane == ldr_) && ((unsigned)(wv) < (unsigned)X);    \
        const int idx_ = ok_ ? (wv) : (X + lane);                             \
        myhist[idx_] = (unsigned short)(myhist[idx_] + cnt_);                 \
    } while (0)

    for (int k = 0; k < kiters; k++) {
        const int i   = k * NT + tid;
        const bool ip = i < n4;
        const int y   = i << 2;
        int4 d = ip ? dur4[i] : make_int4(-1, -1, -1, -1);

        const bool v0 = (y + 0) < L;
        const bool v1 = (y + 1) < L;
        const bool v2 = (y + 2) < L;
        const bool v3 = (y + 3) < L;

        if (ip) {
            float4 w;
            w.x = __uint_as_float((unsigned)d.x + (v0 ? C_VALID : C_MASKED)) - FBIAS;
            w.y = __uint_as_float((unsigned)d.y + (v1 ? C_VALID : C_MASKED)) - FBIAS;
            w.z = __uint_as_float((unsigned)d.z + (v2 ? C_VALID : C_MASKED)) - FBIAS;
            w.w = __uint_as_float((unsigned)d.w + (v3 ? C_VALID : C_MASKED)) - FBIAS;
            w4[i] = w;
        }

        // Histogram values: invalid/masked lanes contribute out-of-range -1.
        const int h0 = (ip && v0) ? d.x : -1;
        const int h1 = (ip && v1) ? d.y : -1;
        const int h2 = (ip && v2) ? d.z : -1;
        const int h3 = (ip && v3) ? d.w : -1;
        HIST_STEP(h0);
        HIST_STEP(h1);
        HIST_STEP(h2);
        HIST_STEP(h3);
    }

    // Scalar tail (Y % 4 != 0); uniform trip count keeps match collective.
    for (int k = 0; k < titers; k++) {
        const int y   = ytail0 + k * NT + tid;
        const bool ip = y < Y;
        int dv = -1;
        if (ip) {
            dv = duration[(size_t)b * Y + y];
            const bool v = y < L;
            w_out[(size_t)b * Y + y] =
                __uint_as_float((unsigned)dv + (v ? C_VALID : C_MASKED)) - FBIAS;
            if (!v) dv = -1;
        }
        HIST_STEP(dv);
    }
    #undef HIST_STEP

    __syncthreads();

    // Merge: 8 bins per thread. Sum NWARP u16x8 rows with packed __vadd2
    // (per-bin total <= Y <= 65535: no 16-bit overflow), then bias-trick
    // to float and store two float4s.
    float* __restrict__ hrow = h_out + (size_t)b * X;
    const int nch = X >> 3;
    for (int c = tid; c < nch; c += NT) {
        const int bin = c << 3;
        unsigned s0 = 0, s1 = 0, s2 = 0, s3 = 0;   // 8 packed u16 sums
        #pragma unroll
        for (int w = 0; w < NWARP; w++) {
            const uint4 v = *reinterpret_cast<const uint4*>(hist16 + w * hstr + bin);
            s0 = __vadd2(s0, v.x);
            s1 = __vadd2(s1, v.y);
            s2 = __vadd2(s2, v.z);
            s3 = __vadd2(s3, v.w);
        }
        float4 o0, o1;
        o0.x = __uint_as_float(C_ZERO + (s0 & 0xFFFFu)) - CBIAS;
        o0.y = __uint_as_float(C_ZERO + (s0 >> 16))     - CBIAS;
        o0.z = __uint_as_float(C_ZERO + (s1 & 0xFFFFu)) - CBIAS;
        o0.w = __uint_as_float(C_ZERO + (s1 >> 16))     - CBIAS;
        o1.x = __uint_as_float(C_ZERO + (s2 & 0xFFFFu)) - CBIAS;
        o1.y = __uint_as_float(C_ZERO + (s2 >> 16))     - CBIAS;
        o1.z = __uint_as_float(C_ZERO + (s3 & 0xFFFFu)) - CBIAS;
        o1.w = __uint_as_float(C_ZERO + (s3 >> 16))     - CBIAS;
        reinterpret_cast<float4*>(hrow)[(c << 1) + 0] = o0;
        reinterpret_cast<float4*>(hrow)[(c << 1) + 1] = o1;
    }
    // Tail bins (X % 8 != 0)
    for (int bin = (X & ~7) + tid; bin < X; bin += NT) {
        unsigned s = 0;
        #pragma unroll
        for (int w = 0; w < NWARP; w++) s += hist16[w * hstr + bin];
        hrow[bin] = __uint_as_float(C_ZERO + s) - CBIAS;
    }
}

// Fallback: proven smem-atomic kernel (R16 shape) for large X.
__global__ void __launch_bounds__(256)
duration_calc_fallback(const int* __restrict__ duration,
                       const int* __restrict__ output_length,
                       float* __restrict__ w_out,
                       float* __restrict__ h_out,
                       int Y, int X)
{
    extern __shared__ int hist[];
    const int b = blockIdx.x, tid = threadIdx.x, nt = blockDim.x;
    for (int i = tid; i < X; i += nt) hist[i] = 0;
    __syncthreads();
    const int L = output_length[b];
    for (int y = tid; y < Y; y += nt) {
        const int d = duration[(size_t)b * Y + y];
        const bool v = y < L;
        w_out[(size_t)b * Y + y] =
            __uint_as_float((unsigned)d + (v ? C_VALID : C_MASKED)) - FBIAS;
        if (v && (unsigned)d < (unsigned)X) atomicAdd(&hist[d], 1);
    }
    __syncthreads();
    float* hrow = h_out + (size_t)b * X;
    for (int i = tid; i < X; i += nt)
        hrow[i] = __uint_as_float(C_ZERO + (unsigned)hist[i]) - CBIAS;
}

extern "C" void kernel_launch(void* const* d_in, const int* in_sizes, int n_in,
                              void* d_out, int out_size)
{
    const int* duration      = (const int*)d_in[0];
    const int* output_length = (const int*)d_in[1];

    const int B = in_sizes[1];          // 256
    const int Y = in_sizes[0] / B;      // 4096
    const int X = out_size / B - Y;     // 1024

    float* w_out = (float*)d_out;                   // weights_argmax: B*Y
    float* h_out = (float*)d_out + (size_t)B * Y;   // durations:      B*X

    const int hstr = ((X + 32 + 7) & ~7);           // u16 stride, 16B-multiple
    const size_t smem = (size_t)NWARP * hstr * sizeof(unsigned short);

    if (smem <= 48 * 1024 && Y <= 65535) {
        duration_calc_kernel<<<B, NT, smem>>>(duration, output_length,
                                              w_out, h_out, Y, X, hstr);
    } else {
        duration_calc_fallback<<<B, 256, (size_t)X * sizeof(int)>>>(
            duration, output_length, w_out, h_out, Y, X);
    }
}